// round 8
// baseline (speedup 1.0000x reference)
#include <cuda_runtime.h>
#include <cuda_fp16.h>

// FernSparseTable_44779329028743
// B:       (32, 160, 64, 64) f32   [d_in[0]]
// weights: (16, 1024, 64)    f32   [d_in[1]]
// bias:    (64,)             f32   [d_in[2]]
// out:     (32, 64, 64, 64)  f32
//
// Per pixel, per fern m: 10 bit-probs -> word index WB, top-3 most ambiguous
// bits, 8 (index, coeff) pairs, gather-accumulate 8 rows of weights[m].
//
// Layout: 1 warp = 2 pixels. Lane = 16*s + m computes fern m for pixel s.
// Gather phase: shfl (idx, coef) from lane 16*s+m; 32 lanes load one 128 B
// fp16 table row coalesced; lane l accumulates output dims (2l, 2l+1).

#define NM 16
#define NK 10
#define HW 4096
#define TAB_ROWS 1024
#define DHALF 32            // 64 dims as 32 half2
#define PIX_PER_BLOCK 16    // 8 warps x 2 pixels

// fp16 copy of the table: [m][row][32] half2  (2 MB -> fully L2 resident)
__device__ __half2 g_wtab[NM * TAB_ROWS * DHALF];

__global__ void convert_weights_kernel(const float* __restrict__ w) {
    int i = blockIdx.x * blockDim.x + threadIdx.x;
    const int n = NM * TAB_ROWS * DHALF;
    if (i < n) {
        float2 f = reinterpret_cast<const float2*>(w)[i];
        g_wtab[i] = __float22half2_rn(f);
    }
}

__global__ __launch_bounds__(256) void fern_kernel(
    const float* __restrict__ B,
    const float* __restrict__ bias,
    float* __restrict__ out)
{
    __shared__ float sB[160 * 17];           // [c][px], px-pad 16->17 (conflict-free)
    __shared__ float sO[PIX_PER_BLOCK * 66]; // [px][d], pad 64->66

    const int tid  = threadIdx.x;
    const int lane = tid & 31;
    const int warp = tid >> 5;          // 0..7
    const int s    = lane >> 4;         // pixel-within-warp (0/1)
    const int m    = lane & 15;         // fern handled by this lane
    const int px   = 2 * warp + s;      // pixel-within-block 0..15

    // block covers 16 consecutive w of one (n, h)
    const int pixBase = blockIdx.x * PIX_PER_BLOCK;
    const int n  = pixBase >> 12;
    const int hw = pixBase & 4095;
    const int h  = hw >> 6;
    const int w0 = hw & 63;             // multiple of 16

    // ---- stage B slab: 160 channels x 16 w's (coalesced 64B groups) ----
    const float* Bbase = B + (size_t)n * 160 * HW + h * 64 + w0;
    #pragma unroll
    for (int i = tid; i < 160 * 16; i += 256) {
        int c = i >> 4, wp = i & 15;
        sB[c * 17 + wp] = Bbase[(size_t)c * HW + wp];
    }
    __syncthreads();

    // ---- phase 1: fern logic (lane 16s+m -> fern m of pixel px) ----
    float t[10], ba[10];
    int wb = 0;
    float bsp = 1.0f;
    #pragma unroll
    for (int k = 0; k < NK; k++) {
        float tk = sB[(m * NK + k) * 17 + px];
        t[k]  = tk;
        wb   |= (tk >= 0.5f) ? (1 << k) : 0;
        bsp  *= fmaxf(tk, 1.0f - tk);
        ba[k] = fabsf(tk - 0.5f);
    }

    // top-3 argmin of |t-0.5|, first-occurrence tie-break (matches jnp.argmin
    // with the reference's BA+=1 exclusion trick)
    int a0 = 0; float v0 = t[0];
    {
        float best = ba[0];
        #pragma unroll
        for (int k = 1; k < NK; k++)
            if (ba[k] < best) { best = ba[k]; a0 = k; v0 = t[k]; }
    }
    int a1 = -1; float v1 = 0.0f;
    {
        float best = 3e38f;
        #pragma unroll
        for (int k = 0; k < NK; k++)
            if (k != a0 && ba[k] < best) { best = ba[k]; a1 = k; v1 = t[k]; }
    }
    int a2 = -1; float v2 = 0.0f;
    {
        float best = 3e38f;
        #pragma unroll
        for (int k = 0; k < NK; k++)
            if (k != a0 && k != a1 && ba[k] < best) { best = ba[k]; a2 = k; v2 = t[k]; }
    }

    // bsp / max(aba, 1-aba) per ambiguous bit
    float sc = bsp;
    sc /= fmaxf(v0, 1.0f - v0);
    sc /= fmaxf(v1, 1.0f - v1);
    sc /= fmaxf(v2, 1.0f - v2);

    const float h0 = v0, l0 = 1.0f - v0;
    const float h1 = v1, l1 = 1.0f - v1;
    const float h2 = v2, l2 = 1.0f - v2;

    // 8 coefficients: bit j of p selects hi_j vs lo_j (product tree)
    float x0 = sc * l0, x1 = sc * h0;
    float y0 = x0 * l1, y1 = x1 * l1, y2 = x0 * h1, y3 = x1 * h1;
    float cw0 = y0 * l2, cw1 = y1 * l2, cw2 = y2 * l2, cw3 = y3 * l2;
    float cw4 = y0 * h2, cw5 = y1 * h2, cw6 = y2 * h2, cw7 = y3 * h2;

    // 8 indices: clear the 3 ambiguous bits, OR back per p
    const int m0 = 1 << a0, m1 = 1 << a1, m2 = 1 << a2;
    const int bse = wb & ~(m0 | m1 | m2);
    int id0 = bse,            id1 = bse | m0;
    int id2 = bse | m1,       id3 = bse | m0 | m1;
    int id4 = id0 | m2,       id5 = id1 | m2;
    int id6 = id2 | m2,       id7 = id3 | m2;

    // ---- phase 2: gather-accumulate. lane l owns output dims (2l, 2l+1) ----
    // acc*0 for pixel 2*warp+0 (source lanes 0..15),
    // acc*1 for pixel 2*warp+1 (source lanes 16..31)
    float accx0 = 0.0f, accy0 = 0.0f, accx1 = 0.0f, accy1 = 0.0f;

#define GSTEP(P, SRC, AX, AY) {                                         \
        int   gidx = __shfl_sync(0xffffffffu, id##P, (SRC));            \
        float gcw  = __shfl_sync(0xffffffffu, cw##P, (SRC));            \
        __half2 hv = __ldg(wm + gidx * DHALF + lane);                   \
        float2  fv = __half22float2(hv);                                \
        AX = fmaf(gcw, fv.x, AX);                                       \
        AY = fmaf(gcw, fv.y, AY); }

    #pragma unroll 4
    for (int mm = 0; mm < NM; mm++) {
        const __half2* wm = g_wtab + (mm << 15);   // mm * 1024 * 32
        GSTEP(0, mm, accx0, accy0) GSTEP(1, mm, accx0, accy0)
        GSTEP(2, mm, accx0, accy0) GSTEP(3, mm, accx0, accy0)
        GSTEP(4, mm, accx0, accy0) GSTEP(5, mm, accx0, accy0)
        GSTEP(6, mm, accx0, accy0) GSTEP(7, mm, accx0, accy0)
        GSTEP(0, 16 + mm, accx1, accy1) GSTEP(1, 16 + mm, accx1, accy1)
        GSTEP(2, 16 + mm, accx1, accy1) GSTEP(3, 16 + mm, accx1, accy1)
        GSTEP(4, 16 + mm, accx1, accy1) GSTEP(5, 16 + mm, accx1, accy1)
        GSTEP(6, 16 + mm, accx1, accy1) GSTEP(7, 16 + mm, accx1, accy1)
    }
#undef GSTEP

    // bias, stage both pixels to smem for grouped stores
    float2 bi = reinterpret_cast<const float2*>(bias)[lane];
    sO[(2 * warp + 0) * 66 + 2 * lane]     = accx0 + bi.x;
    sO[(2 * warp + 0) * 66 + 2 * lane + 1] = accy0 + bi.y;
    sO[(2 * warp + 1) * 66 + 2 * lane]     = accx1 + bi.x;
    sO[(2 * warp + 1) * 66 + 2 * lane + 1] = accy1 + bi.y;
    __syncthreads();

    // ---- write out (N, D, H, W): 16 consecutive w per d ----
    float* obase = out + (size_t)n * 64 * HW + h * 64 + w0;
    #pragma unroll
    for (int i = tid; i < 64 * 16; i += 256) {
        int d = i >> 4, wp = i & 15;
        obase[(size_t)d * HW + wp] = sO[wp * 66 + d];
    }
}

extern "C" void kernel_launch(void* const* d_in, const int* in_sizes, int n_in,
                              void* d_out, int out_size) {
    const float* B    = (const float*)d_in[0];
    const float* Wts  = (const float*)d_in[1];
    const float* bias = (const float*)d_in[2];
    float* out = (float*)d_out;

    // 16*1024*32 = 524288 half2 elements
    convert_weights_kernel<<<2048, 256>>>(Wts);

    // 131072 pixels / 16 per block
    fern_kernel<<<8192, 256>>>(B, bias, out);
}

// round 15
// speedup vs baseline: 1.2710x; 1.2710x over previous
#include <cuda_runtime.h>
#include <cuda_fp16.h>

// FernSparseTable_44779329028743
// B:       (32, 160, 64, 64) f32   [d_in[0]]
// weights: (16, 1024, 64)    f32   [d_in[1]]
// bias:    (64,)             f32   [d_in[2]]
// out:     (32, 64, 64, 64)  f32
//
// R8 profile: issue 78%, L1 73% (LSU dispatch + wavefronts), L2 33%, DRAM 5%.
// LDG.64 row-pairing: half-warp h serves pixel h; lane 16h+j loads uint2
// (dims 4j..4j+3) of its pixel's table row; one LDG.64 fetches both pixels'
// rows. Shfl src (mm | (lane&16)) feeds both halves.
// R13 FIX: fern byte-stride is 1024 rows * 128 B = 131072 (was 32768, a
// half2-element count left over from the R8 indexing — caused rel_err 8.5e-2).

#define NM 16
#define NK 10
#define HW 4096
#define PIX_PER_BLOCK 16    // 8 warps x 2 pixels
#define FERN_BYTES (1024 * 128)   // 131072 B per fern table

// fp16 copy of the table: [m][row][16 x uint2(4 halves)]  (2 MB, L2-resident)
__device__ uint2 g_wtab[NM * 1024 * 16];

__global__ void convert_weights_kernel(const float* __restrict__ w) {
    int i = blockIdx.x * blockDim.x + threadIdx.x;
    if (i < NM * 1024 * 16) {
        float4 f = reinterpret_cast<const float4*>(w)[i];
        __half2 a = __floats2half2_rn(f.x, f.y);
        __half2 b = __floats2half2_rn(f.z, f.w);
        uint2 u;
        u.x = *reinterpret_cast<unsigned*>(&a);
        u.y = *reinterpret_cast<unsigned*>(&b);
        g_wtab[i] = u;
    }
}

__global__ __launch_bounds__(256) void fern_kernel(
    const float* __restrict__ B,
    const float* __restrict__ bias,
    float* __restrict__ out)
{
    __shared__ float sB[160 * 17];           // [c][px], px-pad 16->17 (conflict-free)
    __shared__ float sO[PIX_PER_BLOCK * 66]; // [px][d], pad 64->66

    const int tid  = threadIdx.x;
    const int lane = tid & 31;
    const int warp = tid >> 5;          // 0..7
    const int s    = lane >> 4;         // pixel-within-warp (0/1)
    const int m    = lane & 15;         // fern handled by this lane (phase 1)
    const int px   = 2 * warp + s;      // pixel-within-block 0..15

    // block covers 16 consecutive w of one (n, h)
    const int pixBase = blockIdx.x * PIX_PER_BLOCK;
    const int n  = pixBase >> 12;
    const int hw = pixBase & 4095;
    const int h  = hw >> 6;
    const int w0 = hw & 63;             // multiple of 16

    // ---- stage B slab: 160 channels x 16 w's (coalesced 64B groups) ----
    const float* Bbase = B + (size_t)n * 160 * HW + h * 64 + w0;
    #pragma unroll
    for (int i = tid; i < 160 * 16; i += 256) {
        int c = i >> 4, wp = i & 15;
        sB[c * 17 + wp] = Bbase[(size_t)c * HW + wp];
    }
    __syncthreads();

    // ---- phase 1: fern logic (lane 16s+m -> fern m of pixel px) ----
    float t[10], ba[10];
    int wb = 0;
    float bsp = 1.0f;
    #pragma unroll
    for (int k = 0; k < NK; k++) {
        float tk = sB[(m * NK + k) * 17 + px];
        t[k]  = tk;
        wb   |= (tk >= 0.5f) ? (1 << k) : 0;
        bsp  *= fmaxf(tk, 1.0f - tk);
        ba[k] = fabsf(tk - 0.5f);
    }

    // top-3 argmin of |t-0.5|, first-occurrence tie-break (matches jnp.argmin
    // with the reference's BA+=1 exclusion trick)
    int a0 = 0; float v0 = t[0];
    {
        float best = ba[0];
        #pragma unroll
        for (int k = 1; k < NK; k++)
            if (ba[k] < best) { best = ba[k]; a0 = k; v0 = t[k]; }
    }
    int a1 = -1; float v1 = 0.0f;
    {
        float best = 3e38f;
        #pragma unroll
        for (int k = 0; k < NK; k++)
            if (k != a0 && ba[k] < best) { best = ba[k]; a1 = k; v1 = t[k]; }
    }
    int a2 = -1; float v2 = 0.0f;
    {
        float best = 3e38f;
        #pragma unroll
        for (int k = 0; k < NK; k++)
            if (k != a0 && k != a1 && ba[k] < best) { best = ba[k]; a2 = k; v2 = t[k]; }
    }

    // bsp / max(aba, 1-aba) per ambiguous bit
    float sc = bsp;
    sc /= fmaxf(v0, 1.0f - v0);
    sc /= fmaxf(v1, 1.0f - v1);
    sc /= fmaxf(v2, 1.0f - v2);

    const float h0 = v0, l0 = 1.0f - v0;
    const float h1 = v1, l1 = 1.0f - v1;
    const float h2 = v2, l2 = 1.0f - v2;

    // 8 coefficients: bit j of p selects hi_j vs lo_j (product tree)
    float x0 = sc * l0, x1 = sc * h0;
    float y0 = x0 * l1, y1 = x1 * l1, y2 = x0 * h1, y3 = x1 * h1;
    float cw0 = y0 * l2, cw1 = y1 * l2, cw2 = y2 * l2, cw3 = y3 * l2;
    float cw4 = y0 * h2, cw5 = y1 * h2, cw6 = y2 * h2, cw7 = y3 * h2;

    // 8 indices: clear the 3 ambiguous bits, OR back per p
    const int m0 = 1 << a0, m1 = 1 << a1, m2 = 1 << a2;
    const int bse = wb & ~(m0 | m1 | m2);
    int id0 = bse,            id1 = bse | m0;
    int id2 = bse | m1,       id3 = bse | m0 | m1;
    int id4 = id0 | m2,       id5 = id1 | m2;
    int id6 = id2 | m2,       id7 = id3 | m2;

    // ---- phase 2: row-paired gather-accumulate ----
    // lane = 16h + j: accumulates dims 4j..4j+3 of pixel (2*warp + h).
    // One LDG.64 per (mm, P) loads both pixels' rows (one 128B row per half-warp).
    const int j      = lane & 15;
    const int srcHi  = lane & 16;       // shfl source offset for this half-warp
    const char* wlane = (const char*)g_wtab + j * 8;

    float acc0 = 0.0f, acc1 = 0.0f, acc2 = 0.0f, acc3 = 0.0f;

#define GSTEP(P) {                                                          \
        int   gidx = __shfl_sync(0xffffffffu, id##P, src);                  \
        float gcw  = __shfl_sync(0xffffffffu, cw##P, src);                  \
        uint2 hv = __ldg(reinterpret_cast<const uint2*>(wm + gidx * 128));  \
        float2 f01 = __half22float2(*reinterpret_cast<__half2*>(&hv.x));    \
        float2 f23 = __half22float2(*reinterpret_cast<__half2*>(&hv.y));    \
        acc0 = fmaf(gcw, f01.x, acc0);                                      \
        acc1 = fmaf(gcw, f01.y, acc1);                                      \
        acc2 = fmaf(gcw, f23.x, acc2);                                      \
        acc3 = fmaf(gcw, f23.y, acc3); }

    #pragma unroll 4
    for (int mm = 0; mm < NM; mm++) {
        const char* wm = wlane + mm * FERN_BYTES;   // mm * 1024 rows * 128 B
        const int src = mm | srcHi;
        GSTEP(0) GSTEP(1) GSTEP(2) GSTEP(3)
        GSTEP(4) GSTEP(5) GSTEP(6) GSTEP(7)
    }
#undef GSTEP

    // bias (dims 4j..4j+3), stage to smem for grouped stores
    const float4 bi = reinterpret_cast<const float4*>(bias)[j];
    sO[px * 66 + 4 * j + 0] = acc0 + bi.x;
    sO[px * 66 + 4 * j + 1] = acc1 + bi.y;
    sO[px * 66 + 4 * j + 2] = acc2 + bi.z;
    sO[px * 66 + 4 * j + 3] = acc3 + bi.w;
    __syncthreads();

    // ---- write out (N, D, H, W): 16 consecutive w per d ----
    float* obase = out + (size_t)n * 64 * HW + h * 64 + w0;
    #pragma unroll
    for (int i = tid; i < 64 * 16; i += 256) {
        int d = i >> 4, wp = i & 15;
        obase[(size_t)d * HW + wp] = sO[wp * 66 + d];
    }
}

extern "C" void kernel_launch(void* const* d_in, const int* in_sizes, int n_in,
                              void* d_out, int out_size) {
    const float* B    = (const float*)d_in[0];
    const float* Wts  = (const float*)d_in[1];
    const float* bias = (const float*)d_in[2];
    float* out = (float*)d_out;

    // 16*1024*16 = 262144 uint2 elements
    convert_weights_kernel<<<1024, 256>>>(Wts);

    // 131072 pixels / 16 per block
    fern_kernel<<<8192, 256>>>(B, bias, out);
}